// round 1
// baseline (speedup 1.0000x reference)
#include <cuda_runtime.h>
#include <math.h>

#define Bb 4
#define Nn 2048
#define Cc 256
#define Hh 4
#define Dd 64
#define SCALE 0.125f   // D^-0.5
#define LDSP 72        // smem row stride (floats): 16B-aligned float4 rows, bank-conflict-free

// Scratch (device globals; no allocations allowed)
__device__ __align__(16) float g_Q[Bb*Hh*Nn*Dd];
__device__ __align__(16) float g_K[Bb*Hh*Nn*Dd];
__device__ __align__(16) float g_V[Bb*Hh*Nn*Dd];
__device__ __align__(16) float g_RP[Bb*Nn*4];      // stride-4 padded, pre-multiplied by pos_scale
__device__ __align__(16) float g_AO[Bb*Nn*Cc];     // attention output before proj

// ---------------------------------------------------------------------------
// RP[b,j,c] = pos_scale * sum_d R[b,c,d] * P[j,d]
// ---------------------------------------------------------------------------
__global__ void rp_kernel(const float* __restrict__ R, const float* __restrict__ P,
                          const float* __restrict__ pos_scale) {
    int idx = blockIdx.x * blockDim.x + threadIdx.x;
    if (idx >= Bb * Nn) return;
    int b = idx / Nn, j = idx % Nn;
    float p0 = P[j*3+0], p1 = P[j*3+1], p2 = P[j*3+2];
    float ps = *pos_scale;
    const float* Rb = R + b*9;
#pragma unroll
    for (int c = 0; c < 3; c++)
        g_RP[idx*4 + c] = ps * (Rb[c*3+0]*p0 + Rb[c*3+1]*p1 + Rb[c*3+2]*p2);
    g_RP[idx*4 + 3] = 0.f;
}

// ---------------------------------------------------------------------------
// NT GEMM: out[m,c] = sum_k A[m,k] * W[c,k] + bias[c]
// 64x64 block tile, 4x4 thread tile, K-tile 16, 256 threads.
// IS_QKV: scatter into g_Q/g_K/g_V per (3,H,D) layout; else write row-major Out.
// ---------------------------------------------------------------------------
template<bool IS_QKV>
__global__ void gemm_nt_kernel(const float* __restrict__ A, const float* __restrict__ W,
                               const float* __restrict__ bias, float* __restrict__ Out,
                               int Kdim) {
    __shared__ __align__(16) float As[16 * LDSP];
    __shared__ __align__(16) float Ws[16 * LDSP];

    const float* Ap;
    if constexpr (IS_QKV) Ap = A; else Ap = g_AO;

    int tid = threadIdx.x;
    int tx = tid & 15, ty = tid >> 4;
    int m0 = blockIdx.y * 64, n0 = blockIdx.x * 64;
    int lm = tid >> 2;          // 0..63
    int k4 = (tid & 3) * 4;     // 0,4,8,12

    float acc[4][4];
#pragma unroll
    for (int r = 0; r < 4; r++)
#pragma unroll
        for (int c = 0; c < 4; c++) acc[r][c] = 0.f;

    for (int k0 = 0; k0 < Kdim; k0 += 16) {
        float4 av = *(const float4*)&Ap[(size_t)(m0 + lm) * Kdim + k0 + k4];
        float4 wv = *(const float4*)&W [(size_t)(n0 + lm) * Kdim + k0 + k4];
        As[(k4+0)*LDSP + lm] = av.x; As[(k4+1)*LDSP + lm] = av.y;
        As[(k4+2)*LDSP + lm] = av.z; As[(k4+3)*LDSP + lm] = av.w;
        Ws[(k4+0)*LDSP + lm] = wv.x; Ws[(k4+1)*LDSP + lm] = wv.y;
        Ws[(k4+2)*LDSP + lm] = wv.z; Ws[(k4+3)*LDSP + lm] = wv.w;
        __syncthreads();
#pragma unroll
        for (int kk = 0; kk < 16; kk++) {
            float a[4], w[4];
            *(float4*)a = *(const float4*)&As[kk*LDSP + ty*4];
            *(float4*)w = *(const float4*)&Ws[kk*LDSP + tx*4];
#pragma unroll
            for (int r = 0; r < 4; r++)
#pragma unroll
                for (int c = 0; c < 4; c++) acc[r][c] += a[r] * w[c];
        }
        __syncthreads();
    }

#pragma unroll
    for (int r = 0; r < 4; r++) {
        int m = m0 + ty*4 + r;
#pragma unroll
        for (int c4 = 0; c4 < 4; c4++) {
            int c = n0 + tx*4 + c4;
            float v = acc[r][c4] + bias[c];
            if constexpr (IS_QKV) {
                int bb = m >> 11;          // m / N
                int n  = m & (Nn - 1);
                int which = c >> 8;        // 0=q 1=k 2=v
                int h = (c >> 6) & (Hh - 1);
                int d = c & (Dd - 1);
                float* dst = (which == 0) ? g_Q : ((which == 1) ? g_K : g_V);
                dst[((size_t)(bb*Hh + h) * Nn + n) * Dd + d] = v;
            } else {
                Out[(size_t)m * Cc + c] = v;
            }
        }
    }
}

// ---------------------------------------------------------------------------
// Flash attention: one CTA per (b, h, 64-row q tile). fp32, online softmax.
// S = Q K^T * SCALE + RP_i . P_j ; O = softmax(S) V
// ---------------------------------------------------------------------------
#define FLASH_SMEM ((4 * 64 * LDSP + 64 * 4 + 64 * 4) * sizeof(float))

__global__ void flash_kernel(const float* __restrict__ Pg) {
    extern __shared__ __align__(16) float sm[];
    float* Qt   = sm;                   // [d][i]  64 x LDSP
    float* Kt   = Qt + 64 * LDSP;       // [d][j]
    float* Vs   = Kt + 64 * LDSP;       // [j][d]
    float* Ps   = Vs + 64 * LDSP;       // [i][j]
    float* rp_s = Ps + 64 * LDSP;       // [i][4]
    float* p_s  = rp_s + 64 * 4;        // [j][4]

    int b = blockIdx.z, h = blockIdx.y;
    int i0 = blockIdx.x * 64;
    int tid = threadIdx.x;
    int tx = tid & 15, ty = tid >> 4;
    int lm = tid >> 2;              // 0..63
    int l4 = (tid & 3) * 4;         // 0,4,8,12

    const float* Qg = g_Q + (size_t)(b*Hh + h) * Nn * Dd;
    const float* Kg = g_K + (size_t)(b*Hh + h) * Nn * Dd;
    const float* Vg = g_V + (size_t)(b*Hh + h) * Nn * Dd;

    // Load Q tile transposed: Qt[d][i]
#pragma unroll
    for (int p = 0; p < 4; p++) {
        int d = l4 + p * 16;
        float4 qv = *(const float4*)&Qg[(size_t)(i0 + lm) * Dd + d];
        Qt[(d+0)*LDSP + lm] = qv.x; Qt[(d+1)*LDSP + lm] = qv.y;
        Qt[(d+2)*LDSP + lm] = qv.z; Qt[(d+3)*LDSP + lm] = qv.w;
    }
    if (tid < 64) {
        const float* rp = &g_RP[((size_t)b * Nn + i0 + tid) * 4];
        rp_s[tid*4+0] = rp[0]; rp_s[tid*4+1] = rp[1]; rp_s[tid*4+2] = rp[2];
    }
    __syncthreads();

    // Per-thread RP rows (constant across kv tiles)
    float rpr[4][3];
#pragma unroll
    for (int r = 0; r < 4; r++) {
        rpr[r][0] = rp_s[(ty*4+r)*4+0];
        rpr[r][1] = rp_s[(ty*4+r)*4+1];
        rpr[r][2] = rp_s[(ty*4+r)*4+2];
    }

    float m_old[4], lsum[4], O[4][4];
#pragma unroll
    for (int r = 0; r < 4; r++) {
        m_old[r] = -INFINITY; lsum[r] = 0.f;
#pragma unroll
        for (int c = 0; c < 4; c++) O[r][c] = 0.f;
    }

    for (int j0 = 0; j0 < Nn; j0 += 64) {
        // Load K transposed, V natural, P coords
#pragma unroll
        for (int p = 0; p < 4; p++) {
            int d = l4 + p * 16;
            float4 kv = *(const float4*)&Kg[(size_t)(j0 + lm) * Dd + d];
            Kt[(d+0)*LDSP + lm] = kv.x; Kt[(d+1)*LDSP + lm] = kv.y;
            Kt[(d+2)*LDSP + lm] = kv.z; Kt[(d+3)*LDSP + lm] = kv.w;
            float4 vv = *(const float4*)&Vg[(size_t)(j0 + lm) * Dd + d];
            *(float4*)&Vs[lm*LDSP + d] = vv;
        }
        if (tid < 64) {
            p_s[tid*4+0] = Pg[(j0+tid)*3+0];
            p_s[tid*4+1] = Pg[(j0+tid)*3+1];
            p_s[tid*4+2] = Pg[(j0+tid)*3+2];
        }
        __syncthreads();

        // GEMM1: S = Q K^T
        float s[4][4];
#pragma unroll
        for (int r = 0; r < 4; r++)
#pragma unroll
            for (int c = 0; c < 4; c++) s[r][c] = 0.f;
#pragma unroll 8
        for (int d = 0; d < 64; d++) {
            float a[4], k[4];
            *(float4*)a = *(const float4*)&Qt[d*LDSP + ty*4];
            *(float4*)k = *(const float4*)&Kt[d*LDSP + tx*4];
#pragma unroll
            for (int r = 0; r < 4; r++)
#pragma unroll
                for (int c = 0; c < 4; c++) s[r][c] += a[r] * k[c];
        }

        // bias + scale
        float pc[4][3];
#pragma unroll
        for (int c = 0; c < 4; c++) {
            pc[c][0] = p_s[(tx*4+c)*4+0];
            pc[c][1] = p_s[(tx*4+c)*4+1];
            pc[c][2] = p_s[(tx*4+c)*4+2];
        }
#pragma unroll
        for (int r = 0; r < 4; r++)
#pragma unroll
            for (int c = 0; c < 4; c++)
                s[r][c] = s[r][c] * SCALE
                        + rpr[r][0]*pc[c][0] + rpr[r][1]*pc[c][1] + rpr[r][2]*pc[c][2];

        // online softmax update per row
#pragma unroll
        for (int r = 0; r < 4; r++) {
            float mt = fmaxf(fmaxf(s[r][0], s[r][1]), fmaxf(s[r][2], s[r][3]));
#pragma unroll
            for (int off = 8; off; off >>= 1)
                mt = fmaxf(mt, __shfl_xor_sync(0xffffffffu, mt, off, 16));
            float m_new = fmaxf(m_old[r], mt);
            float alpha = __expf(m_old[r] - m_new);
            float rsum = 0.f;
#pragma unroll
            for (int c = 0; c < 4; c++) {
                float pv = __expf(s[r][c] - m_new);
                s[r][c] = pv;
                rsum += pv;
            }
#pragma unroll
            for (int off = 8; off; off >>= 1)
                rsum += __shfl_xor_sync(0xffffffffu, rsum, off, 16);
            lsum[r] = lsum[r] * alpha + rsum;
            m_old[r] = m_new;
#pragma unroll
            for (int c = 0; c < 4; c++) O[r][c] *= alpha;
            // stash P tile
#pragma unroll
            for (int c = 0; c < 4; c++)
                Ps[(ty*4+r)*LDSP + tx*4 + c] = s[r][c];
        }
        __syncthreads();

        // GEMM2: O += P V
#pragma unroll 8
        for (int j = 0; j < 64; j++) {
            float pf[4];
#pragma unroll
            for (int r = 0; r < 4; r++) pf[r] = Ps[(ty*4+r)*LDSP + j];
            float v[4];
            *(float4*)v = *(const float4*)&Vs[j*LDSP + tx*4];
#pragma unroll
            for (int r = 0; r < 4; r++)
#pragma unroll
                for (int c = 0; c < 4; c++) O[r][c] += pf[r] * v[c];
        }
        __syncthreads();
    }

    // epilogue: normalize, write (B,N,H*D)
#pragma unroll
    for (int r = 0; r < 4; r++) {
        int n = i0 + ty*4 + r;
        float inv = 1.f / lsum[r];
#pragma unroll
        for (int c = 0; c < 4; c++)
            g_AO[((size_t)b * Nn + n) * Cc + h*Dd + tx*4 + c] = O[r][c] * inv;
    }
}

// ---------------------------------------------------------------------------
extern "C" void kernel_launch(void* const* d_in, const int* in_sizes, int n_in,
                              void* d_out, int out_size) {
    const float* x         = (const float*)d_in[0];
    const float* R         = (const float*)d_in[1];
    const float* P         = (const float*)d_in[2];
    const float* qkv_w     = (const float*)d_in[3];
    const float* qkv_b     = (const float*)d_in[4];
    const float* proj_w    = (const float*)d_in[5];
    const float* proj_b    = (const float*)d_in[6];
    const float* pos_scale = (const float*)d_in[7];
    float* out = (float*)d_out;

    cudaFuncSetAttribute(flash_kernel, cudaFuncAttributeMaxDynamicSharedMemorySize,
                         (int)FLASH_SMEM);

    rp_kernel<<<(Bb*Nn + 255) / 256, 256>>>(R, P, pos_scale);

    // QKV: M=8192, Ncols=768, K=256
    gemm_nt_kernel<true><<<dim3(768/64, (Bb*Nn)/64), 256>>>(x, qkv_w, qkv_b, nullptr, Cc);

    // Attention
    flash_kernel<<<dim3(Nn/64, Hh, Bb), 256, FLASH_SMEM>>>(P);

    // Proj: M=8192, Ncols=256, K=256 (reads g_AO internally)
    gemm_nt_kernel<false><<<dim3(Cc/64, (Bb*Nn)/64), 256>>>(nullptr, proj_w, proj_b, out, Cc);
}

// round 2
// speedup vs baseline: 1.1873x; 1.1873x over previous
#include <cuda_runtime.h>
#include <math.h>

typedef unsigned long long u64;

#define Bb 4
#define Nn 2048
#define Cc 256
#define Hh 4
#define Dd 64
#define SCALE 0.125f   // D^-0.5

// f32x2 packed helpers (Blackwell sm_100+)
__device__ __forceinline__ u64 dup2(float v) {
    u64 r; asm("mov.b64 %0,{%1,%1};" : "=l"(r) : "f"(v)); return r;
}
__device__ __forceinline__ u64 fma2(u64 a, u64 b, u64 c) {
    u64 d; asm("fma.rn.f32x2 %0,%1,%2,%3;" : "=l"(d) : "l"(a), "l"(b), "l"(c)); return d;
}
__device__ __forceinline__ u64 mul2(u64 a, u64 b) {
    u64 d; asm("mul.rn.f32x2 %0,%1,%2;" : "=l"(d) : "l"(a), "l"(b)); return d;
}
__device__ __forceinline__ float2 unpk(u64 p) {
    float2 f; asm("mov.b64 {%0,%1},%2;" : "=f"(f.x), "=f"(f.y) : "l"(p)); return f;
}

// Scratch (device globals; no allocations allowed)
__device__ __align__(16) float g_Q[Bb*Hh*Nn*Dd];
__device__ __align__(16) float g_K[Bb*Hh*Nn*Dd];
__device__ __align__(16) float g_V[Bb*Hh*Nn*Dd];
__device__ __align__(16) float g_RP[Bb*Nn*4];      // pre-multiplied by pos_scale
__device__ __align__(16) float g_AO[Bb*Nn*Cc];     // attention output before proj

// ---------------------------------------------------------------------------
// RP[b,j,c] = pos_scale * sum_d R[b,c,d] * P[j,d]
// ---------------------------------------------------------------------------
__global__ void rp_kernel(const float* __restrict__ R, const float* __restrict__ P,
                          const float* __restrict__ pos_scale) {
    int idx = blockIdx.x * blockDim.x + threadIdx.x;
    if (idx >= Bb * Nn) return;
    int b = idx / Nn, j = idx % Nn;
    float p0 = P[j*3+0], p1 = P[j*3+1], p2 = P[j*3+2];
    float ps = *pos_scale;
    const float* Rb = R + b*9;
#pragma unroll
    for (int c = 0; c < 3; c++)
        g_RP[idx*4 + c] = ps * (Rb[c*3+0]*p0 + Rb[c*3+1]*p1 + Rb[c*3+2]*p2);
    g_RP[idx*4 + 3] = 0.f;
}

// ---------------------------------------------------------------------------
// NT GEMM (f32x2): out[m,c] = sum_k A[m,k] * W[c,k] + bias[c]
// 128x128 CTA tile, 8x8 thread tile, K-tile 16, 256 threads.
// ---------------------------------------------------------------------------
#define SG 132   // smem k-major stride

template<bool IS_QKV>
__global__ __launch_bounds__(256)
void gemm2_kernel(const float* __restrict__ A, const float* __restrict__ W,
                  const float* __restrict__ bias, float* __restrict__ Out) {
    __shared__ __align__(16) float As[16 * SG];
    __shared__ __align__(16) float Ws[16 * SG];

    const float* Ap;
    if constexpr (IS_QKV) Ap = A; else Ap = g_AO;

    int tid = threadIdx.x;
    int tx = tid & 15, ty = tid >> 4;
    int m0 = blockIdx.y * 128, n0 = blockIdx.x * 128;
    int lr = tid >> 1;            // 0..127
    int kq = (tid & 1) * 8;       // 0 or 8

    u64 acc[8][4];
#pragma unroll
    for (int r = 0; r < 8; r++)
#pragma unroll
        for (int c = 0; c < 4; c++) acc[r][c] = 0ull;

    for (int k0 = 0; k0 < Cc; k0 += 16) {
        float4 a0 = *(const float4*)&Ap[(size_t)(m0 + lr) * Cc + k0 + kq];
        float4 a1 = *(const float4*)&Ap[(size_t)(m0 + lr) * Cc + k0 + kq + 4];
        float4 w0 = *(const float4*)&W [(size_t)(n0 + lr) * Cc + k0 + kq];
        float4 w1 = *(const float4*)&W [(size_t)(n0 + lr) * Cc + k0 + kq + 4];
        As[(kq+0)*SG+lr]=a0.x; As[(kq+1)*SG+lr]=a0.y; As[(kq+2)*SG+lr]=a0.z; As[(kq+3)*SG+lr]=a0.w;
        As[(kq+4)*SG+lr]=a1.x; As[(kq+5)*SG+lr]=a1.y; As[(kq+6)*SG+lr]=a1.z; As[(kq+7)*SG+lr]=a1.w;
        Ws[(kq+0)*SG+lr]=w0.x; Ws[(kq+1)*SG+lr]=w0.y; Ws[(kq+2)*SG+lr]=w0.z; Ws[(kq+3)*SG+lr]=w0.w;
        Ws[(kq+4)*SG+lr]=w1.x; Ws[(kq+5)*SG+lr]=w1.y; Ws[(kq+6)*SG+lr]=w1.z; Ws[(kq+7)*SG+lr]=w1.w;
        __syncthreads();
#pragma unroll
        for (int kk = 0; kk < 16; kk++) {
            float a[8];
            *(float4*)(a+0) = *(const float4*)&As[kk*SG + ty*8];
            *(float4*)(a+4) = *(const float4*)&As[kk*SG + ty*8 + 4];
            ulonglong2 b01 = *(const ulonglong2*)&Ws[kk*SG + tx*8];
            ulonglong2 b23 = *(const ulonglong2*)&Ws[kk*SG + tx*8 + 4];
            u64 B[4] = {b01.x, b01.y, b23.x, b23.y};
            u64 a2[8];
#pragma unroll
            for (int r = 0; r < 8; r++) a2[r] = dup2(a[r]);
#pragma unroll
            for (int r = 0; r < 8; r++)
#pragma unroll
                for (int c = 0; c < 4; c++) acc[r][c] = fma2(a2[r], B[c], acc[r][c]);
        }
        __syncthreads();
    }

#pragma unroll
    for (int r = 0; r < 8; r++) {
        int m = m0 + ty*8 + r;
#pragma unroll
        for (int cp = 0; cp < 4; cp++) {
            float2 v = unpk(acc[r][cp]);
            int c0 = n0 + tx*8 + cp*2;
            float o0 = v.x + bias[c0];
            float o1 = v.y + bias[c0+1];
            if constexpr (IS_QKV) {
#pragma unroll
                for (int e = 0; e < 2; e++) {
                    int c = c0 + e;
                    float val = e ? o1 : o0;
                    int bb = m >> 11;
                    int n  = m & (Nn - 1);
                    int which = c >> 8;
                    int h = (c >> 6) & (Hh - 1);
                    int d = c & (Dd - 1);
                    float* dst = (which == 0) ? g_Q : ((which == 1) ? g_K : g_V);
                    dst[((size_t)(bb*Hh + h) * Nn + n) * Dd + d] = val;
                }
            } else {
                Out[(size_t)m * Cc + c0] = o0;
                Out[(size_t)m * Cc + c0 + 1] = o1;
            }
        }
    }
}

// ---------------------------------------------------------------------------
// Flash attention (f32x2): one CTA per (b, h, 128-row q tile). 128-wide kv tiles.
// S = Q K^T * SCALE + RP_i . P_j ; O = softmax(S) V
// 256 threads, 8x8 per-thread S tile, 8x4 per-thread O tile.
// ---------------------------------------------------------------------------
#define SQ 132   // Qt/Kt stride (d-major)
#define SV 72    // Vs stride (j-major)
#define SP 136   // Ps stride (i-major)
#define FLASH_FLOATS (64*SQ*2 + 128*SV + 128*SP + 512 + 512)
#define FLASH_SMEM (FLASH_FLOATS * sizeof(float))

__global__ __launch_bounds__(256, 1)
void flash2_kernel(const float* __restrict__ Pg) {
    extern __shared__ __align__(16) float sm[];
    float* Qt   = sm;                  // [d][i]   64 x SQ
    float* Kt   = Qt + 64 * SQ;        // [d][j]   64 x SQ
    float* Vs   = Kt + 64 * SQ;        // [j][d]  128 x SV
    float* Ps   = Vs + 128 * SV;       // [i][j]  128 x SP
    float* rp_s = Ps + 128 * SP;       // [i][4]
    float* p_s  = rp_s + 512;          // [j][4]

    int b = blockIdx.z, h = blockIdx.y;
    int i0 = blockIdx.x * 128;
    int tid = threadIdx.x;
    int tx = tid & 15, ty = tid >> 4;
    int lr = tid >> 1;              // 0..127
    int half = (tid & 1) * 32;      // d half

    const float* Qg = g_Q + (size_t)(b*Hh + h) * Nn * Dd;
    const float* Kg = g_K + (size_t)(b*Hh + h) * Nn * Dd;
    const float* Vg = g_V + (size_t)(b*Hh + h) * Nn * Dd;

    // Load Q tile transposed: Qt[d][i]
#pragma unroll
    for (int p = 0; p < 8; p++) {
        int d = half + p * 4;
        float4 q = *(const float4*)&Qg[(size_t)(i0 + lr) * Dd + d];
        Qt[(d+0)*SQ + lr] = q.x; Qt[(d+1)*SQ + lr] = q.y;
        Qt[(d+2)*SQ + lr] = q.z; Qt[(d+3)*SQ + lr] = q.w;
    }
    if (tid < 128) {
        const float* rp = &g_RP[((size_t)b * Nn + i0 + tid) * 4];
        rp_s[tid*4+0] = rp[0]; rp_s[tid*4+1] = rp[1]; rp_s[tid*4+2] = rp[2];
    }
    __syncthreads();

    float m_old[8], lsum[8];
    u64 O2[8][2];
#pragma unroll
    for (int r = 0; r < 8; r++) {
        m_old[r] = -INFINITY; lsum[r] = 0.f;
        O2[r][0] = 0ull; O2[r][1] = 0ull;
    }

    for (int j0 = 0; j0 < Nn; j0 += 128) {
        // Load K transposed, V natural, P coords
#pragma unroll
        for (int p = 0; p < 8; p++) {
            int d = half + p * 4;
            float4 kv = *(const float4*)&Kg[(size_t)(j0 + lr) * Dd + d];
            Kt[(d+0)*SQ + lr] = kv.x; Kt[(d+1)*SQ + lr] = kv.y;
            Kt[(d+2)*SQ + lr] = kv.z; Kt[(d+3)*SQ + lr] = kv.w;
            float4 vv = *(const float4*)&Vg[(size_t)(j0 + lr) * Dd + d];
            *(float4*)&Vs[lr*SV + d] = vv;
        }
        if (tid < 128) {
            p_s[tid*4+0] = Pg[(j0+tid)*3+0];
            p_s[tid*4+1] = Pg[(j0+tid)*3+1];
            p_s[tid*4+2] = Pg[(j0+tid)*3+2];
        }
        __syncthreads();

        // GEMM1: S = Q K^T (8x8 per thread, f32x2 over col pairs)
        u64 s2[8][4];
#pragma unroll
        for (int r = 0; r < 8; r++)
#pragma unroll
            for (int c = 0; c < 4; c++) s2[r][c] = 0ull;

#pragma unroll 8
        for (int d = 0; d < 64; d++) {
            float a[8];
            *(float4*)(a+0) = *(const float4*)&Qt[d*SQ + ty*8];
            *(float4*)(a+4) = *(const float4*)&Qt[d*SQ + ty*8 + 4];
            ulonglong2 b01 = *(const ulonglong2*)&Kt[d*SQ + tx*8];
            ulonglong2 b23 = *(const ulonglong2*)&Kt[d*SQ + tx*8 + 4];
            u64 B[4] = {b01.x, b01.y, b23.x, b23.y};
            u64 a2[8];
#pragma unroll
            for (int r = 0; r < 8; r++) a2[r] = dup2(a[r]);
#pragma unroll
            for (int r = 0; r < 8; r++)
#pragma unroll
                for (int c = 0; c < 4; c++) s2[r][c] = fma2(a2[r], B[c], s2[r][c]);
        }

        // unpack, scale + bias
        float s[8][8];
#pragma unroll
        for (int r = 0; r < 8; r++)
#pragma unroll
            for (int cp = 0; cp < 4; cp++) {
                float2 v = unpk(s2[r][cp]);
                s[r][cp*2]   = v.x;
                s[r][cp*2+1] = v.y;
            }
        float rp0[8], rp1[8], rp2[8];
#pragma unroll
        for (int r = 0; r < 8; r++) {
            int row = ty*8 + r;
            rp0[r] = rp_s[row*4+0]; rp1[r] = rp_s[row*4+1]; rp2[r] = rp_s[row*4+2];
        }
#pragma unroll
        for (int c = 0; c < 8; c++) {
            int col = tx*8 + c;
            float p0 = p_s[col*4+0], p1 = p_s[col*4+1], p2 = p_s[col*4+2];
#pragma unroll
            for (int r = 0; r < 8; r++)
                s[r][c] = s[r][c]*SCALE + rp0[r]*p0 + rp1[r]*p1 + rp2[r]*p2;
        }

        // online softmax (rows owned by 16-lane segments)
#pragma unroll
        for (int r = 0; r < 8; r++) {
            float mt = s[r][0];
#pragma unroll
            for (int c = 1; c < 8; c++) mt = fmaxf(mt, s[r][c]);
#pragma unroll
            for (int off = 8; off; off >>= 1)
                mt = fmaxf(mt, __shfl_xor_sync(0xffffffffu, mt, off, 16));
            float m_new = fmaxf(m_old[r], mt);
            float alpha = __expf(m_old[r] - m_new);
            float rsum = 0.f;
#pragma unroll
            for (int c = 0; c < 8; c++) {
                float pv = __expf(s[r][c] - m_new);
                s[r][c] = pv;
                rsum += pv;
            }
#pragma unroll
            for (int off = 8; off; off >>= 1)
                rsum += __shfl_xor_sync(0xffffffffu, rsum, off, 16);
            lsum[r] = lsum[r] * alpha + rsum;
            m_old[r] = m_new;
            u64 al2 = dup2(alpha);
            O2[r][0] = mul2(O2[r][0], al2);
            O2[r][1] = mul2(O2[r][1], al2);
            // stash exp(S) tile
            float* prow = &Ps[(ty*8 + r)*SP + tx*8];
            *(float2*)(prow+0) = make_float2(s[r][0], s[r][1]);
            *(float2*)(prow+2) = make_float2(s[r][2], s[r][3]);
            *(float2*)(prow+4) = make_float2(s[r][4], s[r][5]);
            *(float2*)(prow+6) = make_float2(s[r][6], s[r][7]);
        }
        __syncthreads();

        // GEMM2: O += P V (8 rows x 4 cols per thread)
#pragma unroll 8
        for (int j = 0; j < 128; j++) {
            ulonglong2 v2 = *(const ulonglong2*)&Vs[j*SV + tx*4];
#pragma unroll
            for (int r = 0; r < 8; r++) {
                u64 pf = dup2(Ps[(ty*8 + r)*SP + j]);
                O2[r][0] = fma2(pf, v2.x, O2[r][0]);
                O2[r][1] = fma2(pf, v2.y, O2[r][1]);
            }
        }
        __syncthreads();
    }

    // epilogue: normalize, write (B,N,H*D)
#pragma unroll
    for (int r = 0; r < 8; r++) {
        int n = i0 + ty*8 + r;
        float inv = 1.f / lsum[r];
        float2 o0 = unpk(O2[r][0]);
        float2 o1 = unpk(O2[r][1]);
        float* dst = &g_AO[((size_t)b * Nn + n) * Cc + h*Dd + tx*4];
        dst[0] = o0.x * inv; dst[1] = o0.y * inv;
        dst[2] = o1.x * inv; dst[3] = o1.y * inv;
    }
}

// ---------------------------------------------------------------------------
extern "C" void kernel_launch(void* const* d_in, const int* in_sizes, int n_in,
                              void* d_out, int out_size) {
    const float* x         = (const float*)d_in[0];
    const float* R         = (const float*)d_in[1];
    const float* P         = (const float*)d_in[2];
    const float* qkv_w     = (const float*)d_in[3];
    const float* qkv_b     = (const float*)d_in[4];
    const float* proj_w    = (const float*)d_in[5];
    const float* proj_b    = (const float*)d_in[6];
    const float* pos_scale = (const float*)d_in[7];
    float* out = (float*)d_out;

    cudaFuncSetAttribute(flash2_kernel, cudaFuncAttributeMaxDynamicSharedMemorySize,
                         (int)FLASH_SMEM);

    rp_kernel<<<(Bb*Nn + 255) / 256, 256>>>(R, P, pos_scale);

    // QKV: M=8192, Ncols=768, K=256
    gemm2_kernel<true><<<dim3(768/128, (Bb*Nn)/128), 256>>>(x, qkv_w, qkv_b, nullptr);

    // Attention
    flash2_kernel<<<dim3(Nn/128, Hh, Bb), 256, FLASH_SMEM>>>(P);

    // Proj: M=8192, Ncols=256, K=256 (reads g_AO internally)
    gemm2_kernel<false><<<dim3(Cc/128, (Bb*Nn)/128), 256>>>(nullptr, proj_w, proj_b, out);
}